// round 4
// baseline (speedup 1.0000x reference)
#include <cuda_runtime.h>
#include <cuda_bf16.h>
#include <cstdint>

// COO SpMM via on-the-fly CSR build (4 kernels), then row-gather SpMM.
// out[i,:] = sum_{e: rows[e]==i} vals[e] * embeds[cols[e],:]

#define N_NODES 100000
#define N_EDGES 1600000
#define D_FEAT  48
#define D_VEC4  12

#define SCAN_N   (N_NODES + 1)          // 100001
#define SCAN_BLK 1024
#define SCAN_NB  ((SCAN_N + SCAN_BLK - 1) / SCAN_BLK)   // 98

// Scratch (static device globals — zero-initialized at module load).
// Invariant: g_counts all-zero at entry (scan re-zeroes after consuming);
// g_desc zeroed by hist block 0 before scan reads it.
__device__ int  g_counts[SCAN_N];
__device__ int  g_offs[SCAN_N];
__device__ int  g_cursor[N_NODES];
__device__ unsigned long long g_desc[SCAN_NB];   // lookback: flag<<62 | sum
__device__ int2 g_edges[N_EDGES];                // {col, val_as_int}

// ---------- pass 1: histogram of rows (int4) + zero lookback state ----------
__global__ void hist_kernel(const int4* __restrict__ rows4, int n4) {
    if (blockIdx.x == 0 && threadIdx.x < SCAN_NB)
        g_desc[threadIdx.x] = 0ULL;
    int i = blockIdx.x * blockDim.x + threadIdx.x;
    if (i < n4) {
        int4 r = __ldg(&rows4[i]);
        atomicAdd(&g_counts[r.x], 1);
        atomicAdd(&g_counts[r.y], 1);
        atomicAdd(&g_counts[r.z], 1);
        atomicAdd(&g_counts[r.w], 1);
    }
}

// ---------- pass 2: single-launch exclusive scan (decoupled lookback) ----------
// 98 blocks, all co-resident on 148+ SMs => lookback is deadlock-free.
__global__ void __launch_bounds__(SCAN_BLK)
scan_lookback_kernel() {
    __shared__ int warp_sums[32];
    __shared__ int s_exclusive;

    int bid = blockIdx.x;
    int i = bid * SCAN_BLK + threadIdx.x;
    int v = (i < SCAN_N) ? g_counts[i] : 0;
    if (i < SCAN_N) g_counts[i] = 0;      // restore zero invariant

    int lane = threadIdx.x & 31, wid = threadIdx.x >> 5;

    int inc = v;
#pragma unroll
    for (int d = 1; d < 32; d <<= 1) {
        int t = __shfl_up_sync(0xffffffffu, inc, d);
        if (lane >= d) inc += t;
    }
    if (lane == 31) warp_sums[wid] = inc;
    __syncthreads();
    if (wid == 0) {
        int s = warp_sums[lane];
#pragma unroll
        for (int d = 1; d < 32; d <<= 1) {
            int t = __shfl_up_sync(0xffffffffu, s, d);
            if (lane >= d) s += t;
        }
        warp_sums[lane] = s;
    }
    __syncthreads();
    int base = (wid > 0) ? warp_sums[wid - 1] : 0;
    int local_excl = base + inc - v;
    int block_sum = warp_sums[31];

    if (threadIdx.x == 0) {
        unsigned long long flag = (bid == 0) ? 2ULL : 1ULL;
        *(volatile unsigned long long*)&g_desc[bid] =
            (flag << 62) | (unsigned long long)(unsigned)block_sum;
        __threadfence();
        if (bid == 0) s_exclusive = 0;
    }

    if (bid > 0 && wid == 0) {
        int exclusive = 0;
        int j = bid - 1;
        while (true) {
            int idx = j - lane;
            int flag, val;
            if (idx >= 0) {
                unsigned long long d;
                do {
                    d = *(volatile unsigned long long*)&g_desc[idx];
                    flag = (int)(d >> 62);
                } while (flag == 0);
                val = (int)(d & 0xffffffffULL);
            } else { flag = 2; val = 0; }
            unsigned mask = __ballot_sync(0xffffffffu, flag == 2);
            int contrib;
            if (mask) {
                int steps = __ffs(mask) - 1;
                contrib = (lane <= steps) ? val : 0;
            } else {
                contrib = val;
            }
#pragma unroll
            for (int d = 16; d; d >>= 1)
                contrib += __shfl_down_sync(0xffffffffu, contrib, d);
            contrib = __shfl_sync(0xffffffffu, contrib, 0);
            exclusive += contrib;
            if (mask) break;
            j -= 32;
        }
        if (lane == 0) {
            __threadfence();
            *(volatile unsigned long long*)&g_desc[bid] =
                (2ULL << 62) | (unsigned long long)(unsigned)(exclusive + block_sum);
            s_exclusive = exclusive;
        }
    }
    __syncthreads();

    int off = s_exclusive + local_excl;
    if (i < SCAN_N) {
        g_offs[i] = off;
        if (i < N_NODES) g_cursor[i] = off;
    }
}

// ---------- pass 3: scatter edges into CSR bins (4 edges/thread) ----------
__global__ void scatter_kernel(const int4* __restrict__ rows4,
                               const int4* __restrict__ cols4,
                               const float4* __restrict__ vals4, int n4) {
    int i = blockIdx.x * blockDim.x + threadIdx.x;
    if (i < n4) {
        int4   r = __ldg(&rows4[i]);
        int4   c = __ldg(&cols4[i]);
        float4 v = __ldg(&vals4[i]);
        // 4 independent atomics -> MLP=4
        int p0 = atomicAdd(&g_cursor[r.x], 1);
        int p1 = atomicAdd(&g_cursor[r.y], 1);
        int p2 = atomicAdd(&g_cursor[r.z], 1);
        int p3 = atomicAdd(&g_cursor[r.w], 1);
        g_edges[p0] = make_int2(c.x, __float_as_int(v.x));
        g_edges[p1] = make_int2(c.y, __float_as_int(v.y));
        g_edges[p2] = make_int2(c.z, __float_as_int(v.z));
        g_edges[p3] = make_int2(c.w, __float_as_int(v.w));
    }
}

// ---------- pass 4: row-gather SpMM (16-lane groups, unroll x4) ----------
__global__ void __launch_bounds__(256)
spmm_csr_kernel(const float4* __restrict__ embeds4,  // [N,12] float4
                float4* __restrict__ out4) {         // [N,12] float4
    int row  = blockIdx.x * 16 + (threadIdx.x >> 4);
    int lane = threadIdx.x & 15;
    if (row >= N_NODES || lane >= 12) return;   // no intra-group comm -> safe

    int s = g_offs[row];
    int t = g_offs[row + 1];

    float ax = 0.f, ay = 0.f, az = 0.f, aw = 0.f;
    int e = s;
    int tail = t - ((t - s) & 3);
    for (; e < tail; e += 4) {
        // 4 independent edge loads + 4 independent gathers in flight
        int2 p0 = __ldg(&g_edges[e]);
        int2 p1 = __ldg(&g_edges[e + 1]);
        int2 p2 = __ldg(&g_edges[e + 2]);
        int2 p3 = __ldg(&g_edges[e + 3]);
        float4 x0 = __ldg(&embeds4[(size_t)p0.x * D_VEC4 + lane]);
        float4 x1 = __ldg(&embeds4[(size_t)p1.x * D_VEC4 + lane]);
        float4 x2 = __ldg(&embeds4[(size_t)p2.x * D_VEC4 + lane]);
        float4 x3 = __ldg(&embeds4[(size_t)p3.x * D_VEC4 + lane]);
        float v0 = __int_as_float(p0.y);
        float v1 = __int_as_float(p1.y);
        float v2 = __int_as_float(p2.y);
        float v3 = __int_as_float(p3.y);
        ax += v0 * x0.x + v1 * x1.x + v2 * x2.x + v3 * x3.x;
        ay += v0 * x0.y + v1 * x1.y + v2 * x2.y + v3 * x3.y;
        az += v0 * x0.z + v1 * x1.z + v2 * x2.z + v3 * x3.z;
        aw += v0 * x0.w + v1 * x1.w + v2 * x2.w + v3 * x3.w;
    }
    for (; e < t; e++) {
        int2 p = __ldg(&g_edges[e]);
        float4 x = __ldg(&embeds4[(size_t)p.x * D_VEC4 + lane]);
        float v = __int_as_float(p.y);
        ax += v * x.x; ay += v * x.y; az += v * x.z; aw += v * x.w;
    }

    out4[(size_t)row * D_VEC4 + lane] = make_float4(ax, ay, az, aw);
}

extern "C" void kernel_launch(void* const* d_in, const int* in_sizes, int n_in,
                              void* d_out, int out_size) {
    const int*   rows   = (const int*)d_in[0];
    const int*   cols   = (const int*)d_in[1];
    const float* vals   = (const float*)d_in[2];
    const float4* embeds4 = (const float4*)d_in[3];
    float4* out4 = (float4*)d_out;

    int n_edges = in_sizes[0];
    int n4 = n_edges / 4;   // 1.6M divisible by 4

    hist_kernel<<<(n4 + 255) / 256, 256>>>((const int4*)rows, n4);
    scan_lookback_kernel<<<SCAN_NB, SCAN_BLK>>>();
    scatter_kernel<<<(n4 + 255) / 256, 256>>>((const int4*)rows, (const int4*)cols,
                                              (const float4*)vals, n4);
    spmm_csr_kernel<<<(N_NODES + 15) / 16, 256>>>(embeds4, out4);
}

// round 5
// speedup vs baseline: 1.0931x; 1.0931x over previous
#include <cuda_runtime.h>
#include <cuda_bf16.h>
#include <cstdint>

// COO SpMM via on-the-fly CSR build, then warp-per-row gather SpMM.
// out[i,:] = sum_{e: rows[e]==i} vals[e] * embeds[cols[e],:]

#define N_NODES 100000
#define N_EDGES 1600000
#define D_FEAT  48

#define SCAN_N   (N_NODES + 1)          // 100001
#define SCAN_BLK 1024
#define SCAN_NB  ((SCAN_N + SCAN_BLK - 1) / SCAN_BLK)   // 98

// Scratch (static device globals — zero-initialized at module load).
// Invariant: g_counts all-zero at entry (scan re-zeroes after consuming);
// g_desc zeroed by hist block 0 before the scan kernel reads it.
__device__ int  g_counts[SCAN_N];
__device__ int  g_offs[SCAN_N];
__device__ int  g_rank[N_EDGES];                 // edge's rank within its row
__device__ unsigned long long g_desc[SCAN_NB];   // lookback: flag<<62 | sum
__device__ int2 g_edges[N_EDGES];                // {col, val_as_int}

// ---------- pass 1: histogram + per-edge rank (int4) + zero lookback state ----------
__global__ void hist_kernel(const int4* __restrict__ rows4, int n4) {
    if (blockIdx.x == 0 && threadIdx.x < SCAN_NB)
        g_desc[threadIdx.x] = 0ULL;
    int i = blockIdx.x * blockDim.x + threadIdx.x;
    if (i < n4) {
        int4 r = __ldg(&rows4[i]);
        int4 k;
        k.x = atomicAdd(&g_counts[r.x], 1);
        k.y = atomicAdd(&g_counts[r.y], 1);
        k.z = atomicAdd(&g_counts[r.z], 1);
        k.w = atomicAdd(&g_counts[r.w], 1);
        ((int4*)g_rank)[i] = k;   // coalesced store of ranks
    }
}

// ---------- pass 2: single-launch exclusive scan (decoupled lookback) ----------
// 98 blocks, all co-resident on 148+ SMs => lookback is deadlock-free.
__global__ void __launch_bounds__(SCAN_BLK)
scan_lookback_kernel() {
    __shared__ int warp_sums[32];
    __shared__ int s_exclusive;

    int bid = blockIdx.x;
    int i = bid * SCAN_BLK + threadIdx.x;
    int v = (i < SCAN_N) ? g_counts[i] : 0;
    if (i < SCAN_N) g_counts[i] = 0;      // restore zero invariant

    int lane = threadIdx.x & 31, wid = threadIdx.x >> 5;

    int inc = v;
#pragma unroll
    for (int d = 1; d < 32; d <<= 1) {
        int t = __shfl_up_sync(0xffffffffu, inc, d);
        if (lane >= d) inc += t;
    }
    if (lane == 31) warp_sums[wid] = inc;
    __syncthreads();
    if (wid == 0) {
        int s = warp_sums[lane];
#pragma unroll
        for (int d = 1; d < 32; d <<= 1) {
            int t = __shfl_up_sync(0xffffffffu, s, d);
            if (lane >= d) s += t;
        }
        warp_sums[lane] = s;
    }
    __syncthreads();
    int base = (wid > 0) ? warp_sums[wid - 1] : 0;
    int local_excl = base + inc - v;
    int block_sum = warp_sums[31];

    if (threadIdx.x == 0) {
        unsigned long long flag = (bid == 0) ? 2ULL : 1ULL;
        *(volatile unsigned long long*)&g_desc[bid] =
            (flag << 62) | (unsigned long long)(unsigned)block_sum;
        __threadfence();
        if (bid == 0) s_exclusive = 0;
    }

    if (bid > 0 && wid == 0) {
        int exclusive = 0;
        int j = bid - 1;
        while (true) {
            int idx = j - lane;
            int flag, val;
            if (idx >= 0) {
                unsigned long long d;
                do {
                    d = *(volatile unsigned long long*)&g_desc[idx];
                    flag = (int)(d >> 62);
                } while (flag == 0);
                val = (int)(d & 0xffffffffULL);
            } else { flag = 2; val = 0; }
            unsigned mask = __ballot_sync(0xffffffffu, flag == 2);
            int contrib;
            if (mask) {
                int steps = __ffs(mask) - 1;
                contrib = (lane <= steps) ? val : 0;
            } else {
                contrib = val;
            }
#pragma unroll
            for (int d = 16; d; d >>= 1)
                contrib += __shfl_down_sync(0xffffffffu, contrib, d);
            contrib = __shfl_sync(0xffffffffu, contrib, 0);
            exclusive += contrib;
            if (mask) break;
            j -= 32;
        }
        if (lane == 0) {
            __threadfence();
            *(volatile unsigned long long*)&g_desc[bid] =
                (2ULL << 62) | (unsigned long long)(unsigned)(exclusive + block_sum);
            s_exclusive = exclusive;
        }
    }
    __syncthreads();

    if (i < SCAN_N) g_offs[i] = s_exclusive + local_excl;
}

// ---------- pass 3: scatter edges into CSR bins (no atomics) ----------
__global__ void scatter_kernel(const int4* __restrict__ rows4,
                               const int4* __restrict__ cols4,
                               const float4* __restrict__ vals4, int n4) {
    int i = blockIdx.x * blockDim.x + threadIdx.x;
    if (i < n4) {
        int4   r = __ldg(&rows4[i]);
        int4   c = __ldg(&cols4[i]);
        float4 v = __ldg(&vals4[i]);
        int4   k = ((const int4*)g_rank)[i];
        // 4 independent plain-load chains (no atomic round-trip)
        int p0 = __ldg(&g_offs[r.x]) + k.x;
        int p1 = __ldg(&g_offs[r.y]) + k.y;
        int p2 = __ldg(&g_offs[r.z]) + k.z;
        int p3 = __ldg(&g_offs[r.w]) + k.w;
        g_edges[p0] = make_int2(c.x, __float_as_int(v.x));
        g_edges[p1] = make_int2(c.y, __float_as_int(v.y));
        g_edges[p2] = make_int2(c.z, __float_as_int(v.z));
        g_edges[p3] = make_int2(c.w, __float_as_int(v.w));
    }
}

// ---------- pass 4: warp-per-row gather SpMM ----------
// Lanes 0-15 handle even edges, lanes 16-31 odd edges of the SAME row
// (no divergence from pairing two random-length rows). Scalar stride-16
// loads (empirically the fastest access pattern). Halves combined via
// shfl_xor(16).
__global__ void __launch_bounds__(256)
spmm_csr_kernel(const float* __restrict__ embeds, float* __restrict__ out) {
    int row = blockIdx.x * 8 + (threadIdx.x >> 5);
    if (row >= N_NODES) return;
    int half = (threadIdx.x >> 4) & 1;
    int lane = threadIdx.x & 15;

    int s = g_offs[row];
    int t = g_offs[row + 1];

    float a0 = 0.f, a1 = 0.f, a2 = 0.f;
    int e = s + half;
    // unroll x2 per half: 4 edges in flight per warp
    for (; e + 2 < t; e += 4) {
        int2 p0 = __ldg(&g_edges[e]);
        int2 p1 = __ldg(&g_edges[e + 2]);
        const float* b0 = embeds + (size_t)p0.x * D_FEAT + lane;
        const float* b1 = embeds + (size_t)p1.x * D_FEAT + lane;
        float x0 = __ldg(b0), x1 = __ldg(b0 + 16), x2 = __ldg(b0 + 32);
        float y0 = __ldg(b1), y1 = __ldg(b1 + 16), y2 = __ldg(b1 + 32);
        float v0 = __int_as_float(p0.y);
        float v1 = __int_as_float(p1.y);
        a0 += v0 * x0 + v1 * y0;
        a1 += v0 * x1 + v1 * y1;
        a2 += v0 * x2 + v1 * y2;
    }
    if (e < t) {
        int2 p = __ldg(&g_edges[e]);
        const float* b = embeds + (size_t)p.x * D_FEAT + lane;
        float v = __int_as_float(p.y);
        a0 += v * __ldg(b); a1 += v * __ldg(b + 16); a2 += v * __ldg(b + 32);
    }

    // combine the two halves (whole warp active: same row, same code path)
    a0 += __shfl_xor_sync(0xffffffffu, a0, 16);
    a1 += __shfl_xor_sync(0xffffffffu, a1, 16);
    a2 += __shfl_xor_sync(0xffffffffu, a2, 16);

    float* o = out + (size_t)row * D_FEAT + lane;
    if (half == 0) { o[0] = a0; o[16] = a1; }
    else           { o[32] = a2; }
}

extern "C" void kernel_launch(void* const* d_in, const int* in_sizes, int n_in,
                              void* d_out, int out_size) {
    const int*   rows   = (const int*)d_in[0];
    const int*   cols   = (const int*)d_in[1];
    const float* vals   = (const float*)d_in[2];
    const float* embeds = (const float*)d_in[3];
    float* out = (float*)d_out;

    int n_edges = in_sizes[0];
    int n4 = n_edges / 4;   // 1.6M divisible by 4

    hist_kernel<<<(n4 + 255) / 256, 256>>>((const int4*)rows, n4);
    scan_lookback_kernel<<<SCAN_NB, SCAN_BLK>>>();
    scatter_kernel<<<(n4 + 255) / 256, 256>>>((const int4*)rows, (const int4*)cols,
                                              (const float4*)vals, n4);
    spmm_csr_kernel<<<(N_NODES + 7) / 8, 256>>>(embeds, out);
}